// round 9
// baseline (speedup 1.0000x reference)
#include <cuda_runtime.h>
#include <cstdint>

#define DDIM    128
#define NMAXPAD 200704
#define NBMAX   784

#define CS      128
#define NCHMAX  1568
#define GSZ     32
#define NGMAX   49
#define CCAP    128
#define GCAP    4096
#define PCAP    4096
#define SCAP    1024
#define MAXIT   48
#define SCANB   96

// ---------------- static scratch ----------------
__device__ unsigned g_keysA[NMAXPAD];
__device__ unsigned g_keysB[NMAXPAD];
__device__ unsigned g_hist[NBMAX * 2048];     // [block][digit]
__device__ unsigned g_prefix[NBMAX * 2048];   // [block][digit]
__device__ unsigned g_digitTotal[2048];
__device__ unsigned g_digitBase[2048];
__device__ double   g_xs[NMAXPAD + 2];
__device__ float    g_xsf[NMAXPAD + 2];

__device__ int g_candLoI[NCHMAX * CCAP];
__device__ int g_candUpI[NCHMAX * CCAP];
__device__ int g_candCntLo[NCHMAX], g_candCntUp[NCHMAX];
__device__ int g_grpLoI[NGMAX * GCAP];
__device__ int g_grpUpI[NGMAX * GCAP];
__device__ int g_grpCntLo[NGMAX], g_grpCntUp[NGMAX];
__device__ int g_preLoI[NGMAX * PCAP];
__device__ int g_preUpI[NGMAX * PCAP];
__device__ int g_preCntLo[NGMAX], g_preCntUp[NGMAX];
__device__ int g_stkLoI[NCHMAX * SCAP];
__device__ int g_stkUpI[NCHMAX * SCAP];

__device__ int g_mn[NMAXPAD + 2];
__device__ int g_mj[NMAXPAD + 2];
__device__ int g_gcm[NMAXPAD + 2];
__device__ int g_lcm[NMAXPAD + 2];
__device__ int   g_segJbLo[NMAXPAD + 2]; __device__ float g_segXbLo[NMAXPAD + 2]; __device__ float g_segCLo[NMAXPAD + 2];
__device__ int   g_segJbUp[NMAXPAD + 2]; __device__ float g_segXbUp[NMAXPAD + 2]; __device__ float g_segCUp[NMAXPAD + 2];

__device__ int      g_low, g_high, g_done, g_count;
__device__ int      g_ig, g_ih, g_nsegLo, g_nsegUp, g_loA, g_loB, g_upA, g_upB;
__device__ double   g_dip;
__device__ unsigned g_scanmaxU;

// Graham push, exact reference pop predicate; xs of top-2 carried in regs.
__device__ __forceinline__ void cpush(int* si, int cap, int& sp,
                                      double& xt, double& xb, int idx, double x)
{
    while (sp >= 2) {
        int tt = si[sp - 1], bb = si[sp - 2];
        if ((x - xt) * (double)(tt - bb) < (xt - xb) * (double)(idx - tt)) break;
        --sp; xt = xb; xb = (sp >= 2) ? g_xs[si[sp - 2]] : 0.0;
    }
    if (sp >= cap) sp = cap - 1;
    si[sp] = idx; ++sp;
    xb = xt; xt = x;
}

// ---------------- projection ----------------
__global__ void proj_kernel(const float* __restrict__ X, const float* __restrict__ P,
                            const int* __restrict__ idx, int N, int NPAD)
{
    int gtid = blockIdx.x * blockDim.x + threadIdx.x;
    int warpId = gtid >> 5, lane = threadIdx.x & 31;
    const float4* p4 = (const float4*)(P + (size_t)(*idx) * DDIM);
    float4 pv = p4[lane];
    if (warpId < N) {
        const float4* x4 = (const float4*)(X + (size_t)warpId * DDIM);
        float4 xv = x4[lane];
        float s = xv.x * pv.x + xv.y * pv.y + xv.z * pv.z + xv.w * pv.w;
        #pragma unroll
        for (int off = 16; off; off >>= 1) s += __shfl_xor_sync(0xffffffffu, s, off);
        if (lane == 0) {
            unsigned b = __float_as_uint(s);
            g_keysA[warpId] = (b & 0x80000000u) ? ~b : (b | 0x80000000u);
        }
    }
    if (gtid < NPAD - N) g_keysA[N + gtid] = 0xFFFFFFFFu;
}

// ---------------- radix sort: 3 passes x 11 bits ----------------
__global__ void hist_kernel(int srcIsA, int shift)
{
    __shared__ unsigned sh[2048];
    const unsigned* in = srcIsA ? g_keysA : g_keysB;
    for (int i = threadIdx.x; i < 2048; i += 256) sh[i] = 0;
    __syncthreads();
    unsigned key = in[blockIdx.x * 256 + threadIdx.x];
    atomicAdd(&sh[(key >> shift) & 2047u], 1u);
    __syncthreads();
    for (int i = threadIdx.x; i < 2048; i += 256)
        g_hist[blockIdx.x * 2048 + i] = sh[i];     // [block][digit] -> coalesced
}

// thread-per-digit linear block-prefix; coalesced across the warp
__global__ void scanD_kernel(int NB)
{
    int d = blockIdx.x * blockDim.x + threadIdx.x;   // 8 x 256 = 2048
    unsigned run = 0;
    for (int b = 0; b < NB; ++b) {
        unsigned v = g_hist[b * 2048 + d];
        g_prefix[b * 2048 + d] = run;
        run += v;
    }
    g_digitTotal[d] = run;
}

__global__ void scanBase_kernel()
{
    int t = threadIdx.x;              // 256 threads x 8 digits each
    unsigned v[8]; unsigned s = 0;
    #pragma unroll
    for (int k = 0; k < 8; ++k) { v[k] = g_digitTotal[t * 8 + k]; s += v[k]; }
    __shared__ unsigned sh[256];
    sh[t] = s; __syncthreads();
    unsigned x = s;
    #pragma unroll
    for (int off = 1; off < 256; off <<= 1) {
        unsigned y = (t >= off) ? sh[t - off] : 0u;
        __syncthreads();
        if (t >= off) x += y;
        sh[t] = x; __syncthreads();
    }
    unsigned excl = x - s;
    #pragma unroll
    for (int k = 0; k < 8; ++k) { g_digitBase[t * 8 + k] = excl; excl += v[k]; }
}

__global__ void scatter_kernel(int srcIsA, int shift)
{
    extern __shared__ unsigned warpHist[];           // [8][2048] = 64 KB
    const unsigned* in  = srcIsA ? g_keysA : g_keysB;
    unsigned*       out = srcIsA ? g_keysB : g_keysA;
    int t = threadIdx.x, w = t >> 5, lane = t & 31;
    for (int i = t; i < 8 * 2048; i += 256) warpHist[i] = 0u;
    __syncthreads();
    unsigned key = in[blockIdx.x * 256 + t];
    unsigned d = (key >> shift) & 2047u;
    unsigned peers = __match_any_sync(0xffffffffu, d);
    unsigned rank = __popc(peers & ((1u << lane) - 1u));
    if (lane == __ffs(peers) - 1) warpHist[w * 2048 + d] = __popc(peers);
    __syncthreads();
    unsigned base = 0;
    for (int w2 = 0; w2 < w; ++w2) base += warpHist[w2 * 2048 + d];
    out[g_digitBase[d] + g_prefix[blockIdx.x * 2048 + d] + base + rank] = key;
}

// ---------------- finalize: sorted keys (in keysB after 3 passes) -> xs/xsf ----
__global__ void finalize_kernel(int N)
{
    int i = blockIdx.x * blockDim.x + threadIdx.x;
    if (i == 0) { g_xs[0] = 0.0; g_xsf[0] = 0.0f; }
    if (i < N) {
        unsigned k = g_keysB[i];
        unsigned b = (k & 0x80000000u) ? (k ^ 0x80000000u) : ~k;
        float f = __uint_as_float(b);
        g_xs[i + 1] = (double)f;
        g_xsf[i + 1] = f;
    }
}

__global__ void dip_init_kernel(float* out, int N)
{
    g_low = 1; g_high = N; g_dip = 1.0;
    g_done = (N < 4 || g_xs[1] == g_xs[N]) ? 1 : 0;
    out[0] = (float)(1.0 / (2.0 * (double)(N > 1 ? N : 1)));
}

// ---------------- one-time hull structure build ----------------
__global__ void chunk_kernel(int N, int NCH)
{
    int t = blockIdx.x * blockDim.x + threadIdx.x;
    if (t >= 2 * NCH) return;
    int side = t >= NCH, c = side ? t - NCH : t;   // upper: c is reversed id
    if (!side) {
        int* si = g_candLoI + (size_t)c * CCAP;
        int sp = 0; double xt = 0.0, xb = 0.0;
        int s = 1 + c * CS, e = s + CS - 1; if (e > N) e = N;
        for (int j = s; j <= e; ++j) cpush(si, CCAP, sp, xt, xb, j, g_xs[j]);
        g_candCntLo[c] = sp;
    } else {
        int cc = NCH - 1 - c;
        int* si = g_candUpI + (size_t)c * CCAP;
        int sp = 0; double xt = 0.0, xb = 0.0;
        int s = 1 + cc * CS, e = s + CS - 1; if (e > N) e = N;
        for (int k = e; k >= s; --k) cpush(si, CCAP, sp, xt, xb, k, g_xs[k]);
        g_candCntUp[c] = sp;
    }
}

__global__ void group_kernel(int N, int NCH, int NG)
{
    int b = blockIdx.x;
    if (threadIdx.x != 0 || b >= 2 * NG) return;
    int side = b >= NG, g = side ? b - NG : b;
    const int* ci = side ? g_candUpI : g_candLoI;
    const int* cn = side ? g_candCntUp : g_candCntLo;
    int* si = (side ? g_grpUpI : g_grpLoI) + (size_t)g * GCAP;
    int sp = 0; double xt = 0.0, xb = 0.0;
    int c0 = g * GSZ, c1 = c0 + GSZ; if (c1 > NCH) c1 = NCH;
    for (int c = c0; c < c1; ++c) {
        int n = cn[c]; if (n > CCAP) n = CCAP;
        const int* li = ci + (size_t)c * CCAP;
        for (int k = 0; k < n; ++k) { int idx = li[k]; cpush(si, GCAP, sp, xt, xb, idx, g_xs[idx]); }
    }
    (side ? g_grpCntUp : g_grpCntLo)[g] = sp;
}

__global__ void prefixg_kernel(int NG)
{
    int b = blockIdx.x;
    if (threadIdx.x != 0 || b >= 2 * NG) return;
    int side = b >= NG, g = side ? b - NG : b;
    const int* gi = side ? g_grpUpI : g_grpLoI;
    const int* gn = side ? g_grpCntUp : g_grpCntLo;
    int* si = (side ? g_preUpI : g_preLoI) + (size_t)g * PCAP;
    int sp = 0; double xt = 0.0, xb = 0.0;
    for (int gg = 0; gg < g; ++gg) {
        int n = gn[gg]; if (n > GCAP) n = GCAP;
        const int* li = gi + (size_t)gg * GCAP;
        for (int k = 0; k < n; ++k) { int idx = li[k]; cpush(si, PCAP, sp, xt, xb, idx, g_xs[idx]); }
    }
    (side ? g_preCntUp : g_preCntLo)[g] = sp;
}

__global__ void mncomp_kernel(int N, int NCH)
{
    int t = blockIdx.x * blockDim.x + threadIdx.x;
    if (t >= 2 * NCH) return;
    int side = t >= NCH, c = side ? t - NCH : t;
    int g = c / GSZ;
    if (!side) {
        int* si = g_stkLoI + (size_t)c * SCAP;
        int sp = g_preCntLo[g]; if (sp > SCAP) sp = SCAP;
        const int* pi = g_preLoI + (size_t)g * PCAP;
        for (int k = 0; k < sp; ++k) si[k] = pi[k];
        double xt = sp ? g_xs[si[sp - 1]] : 0.0, xb = sp >= 2 ? g_xs[si[sp - 2]] : 0.0;
        for (int cc = g * GSZ; cc < c; ++cc) {
            int n = g_candCntLo[cc]; if (n > CCAP) n = CCAP;
            const int* li = g_candLoI + (size_t)cc * CCAP;
            for (int k = 0; k < n; ++k) { int idx = li[k]; cpush(si, SCAP, sp, xt, xb, idx, g_xs[idx]); }
        }
        int s = 1 + c * CS, e = s + CS - 1; if (e > N) e = N;
        for (int j = s; j <= e; ++j) {
            double x = g_xs[j];
            while (sp >= 2) {
                int tt = si[sp - 1], bb = si[sp - 2];
                if ((x - xt) * (double)(tt - bb) < (xt - xb) * (double)(j - tt)) break;
                --sp; xt = xb; xb = (sp >= 2) ? g_xs[si[sp - 2]] : 0.0;
            }
            g_mn[j] = sp ? si[sp - 1] : j;
            if (sp >= SCAP) sp = SCAP - 1;
            si[sp] = j; ++sp; xb = xt; xt = x;
        }
    } else {
        int cc = NCH - 1 - c;
        int* si = g_stkUpI + (size_t)c * SCAP;
        int sp = g_preCntUp[g]; if (sp > SCAP) sp = SCAP;
        const int* pi = g_preUpI + (size_t)g * PCAP;
        for (int k = 0; k < sp; ++k) si[k] = pi[k];
        double xt = sp ? g_xs[si[sp - 1]] : 0.0, xb = sp >= 2 ? g_xs[si[sp - 2]] : 0.0;
        for (int rr = g * GSZ; rr < c; ++rr) {
            int n = g_candCntUp[rr]; if (n > CCAP) n = CCAP;
            const int* li = g_candUpI + (size_t)rr * CCAP;
            for (int k = 0; k < n; ++k) { int idx = li[k]; cpush(si, SCAP, sp, xt, xb, idx, g_xs[idx]); }
        }
        int s = 1 + cc * CS, e = s + CS - 1; if (e > N) e = N;
        for (int k = e; k >= s; --k) {
            double x = g_xs[k];
            while (sp >= 2) {
                int tt = si[sp - 1], bb = si[sp - 2];
                if ((x - xt) * (double)(tt - bb) < (xt - xb) * (double)(k - tt)) break;
                --sp; xt = xb; xb = (sp >= 2) ? g_xs[si[sp - 2]] : 0.0;
            }
            g_mj[k] = sp ? si[sp - 1] : k;
            if (sp >= SCAP) sp = SCAP - 1;
            si[sp] = k; ++sp; xb = xt; xt = x;
        }
    }
}

// ---------------- per-iteration: chains + zigzag + segment setup ----------------
__global__ void __launch_bounds__(128, 1) iterA_kernel(int N)
{
    if (g_done) return;
    int tid = threadIdx.x;
    __shared__ int s_ig, s_ih, s_lg, s_ll;
    if (tid == 0) {
        const double* xs = g_xs;
        int low = g_low, high = g_high;
        int bad = 0;

        g_gcm[1] = high;
        int i = 1;
        while (g_gcm[i] > low && i < NMAXPAD) {
            int nxt = g_mn[g_gcm[i]];
            if (nxt >= g_gcm[i]) { bad = 1; break; }
            g_gcm[i + 1] = nxt; ++i;
        }
        int l_gcm = i;

        g_lcm[1] = low;
        i = 1;
        while (g_lcm[i] < high && i < NMAXPAD) {
            int nxt = g_mj[g_lcm[i]];
            if (nxt <= g_lcm[i]) { bad = 1; break; }
            g_lcm[i + 1] = nxt; ++i;
        }
        int l_lcm = i;

        int ig = l_gcm, ih = l_lcm, ix = l_gcm - 1, iv = 2;
        double d = 0.0;
        if (!bad && (l_gcm != 2 || l_lcm != 2)) {
            int guard = 4 * (l_gcm + l_lcm) + 64;
            while (guard-- > 0) {
                int gcmix = g_gcm[ix], lcmiv = g_lcm[iv];
                if (gcmix > lcmiv) {
                    int gcmi1 = g_gcm[ix + 1];
                    double tv = ((double)lcmiv - (double)gcmi1 + 1.0)
                              - (xs[lcmiv] - xs[gcmi1]) * (double)(gcmix - gcmi1) / (xs[gcmix] - xs[gcmi1]);
                    ++iv;
                    if (tv >= d) { d = tv; ig = ix + 1; ih = iv - 1; }
                } else {
                    int lcmiv1 = g_lcm[iv - 1];
                    double tv = (xs[gcmix] - xs[lcmiv1]) * (double)(lcmiv - lcmiv1) / (xs[lcmiv] - xs[lcmiv1])
                              - ((double)gcmix - (double)lcmiv1 - 1.0);
                    --ix;
                    if (tv > d) { d = tv; ig = ix + 1; ih = iv; }
                }
                if (ix < 1) ix = 1;
                if (iv > l_lcm) iv = l_lcm;
                if (g_gcm[ix] == g_lcm[iv]) break;
            }
            if (guard <= 0) bad = 1;
        } else if (!bad) {
            d = 1.0;
        }

        s_ig = ig; s_ih = ih; s_lg = l_gcm; s_ll = l_lcm;
        g_ig = ig; g_ih = ih;
        g_nsegLo = l_gcm - ig; g_nsegUp = l_lcm - ih;
        g_loA = g_gcm[l_gcm]; g_loB = g_gcm[ig];
        g_upA = g_lcm[ih];    g_upB = g_lcm[l_lcm];
        g_scanmaxU = 0u; g_count = 0;
        if (bad || d < g_dip) g_done = 1;
    }
    __syncthreads();
    if (g_done) return;
    int ig = s_ig, ih = s_ih, lg = s_lg, ll = s_ll;
    for (int s = tid; s < lg - ig; s += 128) {
        int j = lg - 1 - s;                 // segments ascending in index
        int jb = g_gcm[j + 1], je = g_gcm[j];
        double C = 0.0;
        if (je - jb > 1 && g_xs[je] != g_xs[jb]) C = (double)(je - jb) / (g_xs[je] - g_xs[jb]);
        g_segJbLo[s] = jb; g_segXbLo[s] = g_xsf[jb]; g_segCLo[s] = (float)C;
    }
    for (int s = tid; s < ll - ih; s += 128) {
        int j = ih + s;
        int jb = g_lcm[j], je = g_lcm[j + 1];
        double C = 0.0;
        if (je - jb > 1 && g_xs[je] != g_xs[jb]) C = (double)(je - jb) / (g_xs[je] - g_xs[jb]);
        g_segJbUp[s] = jb; g_segXbUp[s] = g_xsf[jb]; g_segCUp[s] = (float)C;
    }
}

// ---------------- per-iteration: fp32 segment-max scan + state update ----------
__global__ void scanB_kernel(float* out, int N)
{
    if (g_done) return;
    int nLo = g_nsegLo, nUp = g_nsegUp;
    int loA = g_loA, upA = g_upA;
    long cntLo = nLo > 0 ? (long)g_loB - loA + 1 : 0;
    long cntUp = nUp > 0 ? (long)g_upB - upA + 1 : 0;
    if (cntLo < 0) cntLo = 0;
    if (cntUp < 0) cntUp = 0;
    long tot = cntLo + cntUp;

    float local = 0.0f;
    long stride = (long)gridDim.x * blockDim.x;
    for (long e = (long)blockIdx.x * blockDim.x + threadIdx.x; e < tot; e += stride) {
        if (e < cntLo) {
            int i = loA + (int)e;
            int a = 0, b = nLo - 1;
            while (a < b) { int m = (a + b + 1) >> 1; if (g_segJbLo[m] <= i) a = m; else b = m - 1; }
            float C = g_segCLo[a];
            if (C != 0.0f) {
                float tv = (float)(i - g_segJbLo[a] + 1) - (g_xsf[i] - g_segXbLo[a]) * C;
                if (tv > local) local = tv;
            }
        } else {
            int i = upA + (int)(e - cntLo);
            int a = 0, b = nUp - 1;
            while (a < b) { int m = (a + b + 1) >> 1; if (g_segJbUp[m] <= i) a = m; else b = m - 1; }
            float C = g_segCUp[a];
            if (C != 0.0f) {
                float tv = (g_xsf[i] - g_segXbUp[a]) * C - (float)(i - g_segJbUp[a] - 1);
                if (tv > local) local = tv;
            }
        }
    }

    __shared__ float red[256];
    int t = threadIdx.x;
    red[t] = local; __syncthreads();
    #pragma unroll
    for (int off = 128; off >= 1; off >>= 1) {
        if (t < off) { float o = red[t + off]; if (o > red[t]) red[t] = o; }
        __syncthreads();
    }
    if (t == 0) {
        if (red[0] > 1.0f)
            atomicMax(&g_scanmaxU, __float_as_uint(red[0]));  // positive floats: uint order == float order
        __threadfence();
        int old = atomicAdd(&g_count, 1);
        if (old == gridDim.x - 1) {   // last arriving block does the scalar update
            double dip = g_dip;
            unsigned u = g_scanmaxU;
            if (u) {
                double sm = (double)__uint_as_float(u);
                if (sm > dip) dip = sm;
            }
            g_dip = dip;
            out[0] = (float)(dip / (2.0 * (double)N));
            int nlow = g_gcm[g_ig], nhigh = g_lcm[g_ih];
            if (nlow == g_low && nhigh == g_high) g_done = 1;
            else { g_low = nlow; g_high = nhigh; }
        }
    }
}

// ---------------- launch ----------------
extern "C" void kernel_launch(void* const* d_in, const int* in_sizes, int n_in,
                              void* d_out, int out_size)
{
    const float* X = (const float*)d_in[0];
    const float* P = (const float*)d_in[1];
    const int* idx = (const int*)d_in[2];
    float* out = (float*)d_out;

    int N = in_sizes[0] / DDIM;
    int NB = (N + 255) / 256;
    int NPAD = NB * 256;
    int NCH = (N + CS - 1) / CS;
    int NG  = (NCH + GSZ - 1) / GSZ;

    static int smemSet = 0;
    if (!smemSet) {
        cudaFuncSetAttribute(scatter_kernel, cudaFuncAttributeMaxDynamicSharedMemorySize, 8 * 2048 * 4);
        smemSet = 1;
    }

    proj_kernel<<<(N + 7) / 8, 256>>>(X, P, idx, N, NPAD);

    // 3 x 11-bit radix: A->B, B->A, A->B  (final sorted order in g_keysB)
    int srcIsA = 1;
    for (int pass = 0; pass < 3; ++pass) {
        int shift = pass * 11;
        hist_kernel<<<NB, 256>>>(srcIsA, shift);
        scanD_kernel<<<8, 256>>>(NB);
        scanBase_kernel<<<1, 256>>>();
        scatter_kernel<<<NB, 256, 8 * 2048 * 4>>>(srcIsA, shift);
        srcIsA ^= 1;
    }

    finalize_kernel<<<(N + 255) / 256, 256>>>(N);
    dip_init_kernel<<<1, 1>>>(out, N);

    // one-time exact mn[] / mj[] build
    chunk_kernel<<<(2 * NCH + 255) / 256, 256>>>(N, NCH);
    group_kernel<<<2 * NG, 32>>>(N, NCH, NG);
    prefixg_kernel<<<2 * NG, 32>>>(NG);
    mncomp_kernel<<<(2 * NCH + 255) / 256, 256>>>(N, NCH);

    // Hartigan loop: 2 kernels per (device-gated) iteration
    for (int it = 0; it < MAXIT; ++it) {
        iterA_kernel<<<1, 128>>>(N);
        scanB_kernel<<<SCANB, 256>>>(out, N);
    }
}